// round 16
// baseline (speedup 1.0000x reference)
#include <cuda_runtime.h>
#include <cuda_bf16.h>

// CRF score: -( sum_i logits[i, tags[i]] + sum_{i>0} transitions[tags[i-1], tags[i]] )
// logits: [S, 50] f32, tags: [S] int (dtype auto-detected int32 vs int64, inline probe),
// transitions: [50, 50] f32. Output: scalar f32.
//
// FINAL, CONVERGED (measured 47.6-47.9us across 8 runs, rel_err 0; best 47.616).
// DRAM random-request bound at the hardware floor:
//  - bytes: 2M mandatory 4B gathers -> ~1.9M distinct 128B-line fetches (~250MB),
//    invariant across 11 layout/cache-op measurements; fetch-granularity knob banned.
//  - rate: ~5.4TB/s at ~68% DRAM-busy with full queues = bank-activate ceiling;
//    MLP/occupancy/ordering proven non-binding (R5-R9).
//  - no L2 reuse exists (lines hit ~1.05x), streaming >=56us, algorithmic
//    reduction impossible (data-dependent gather).
// Warp-interleaved tiles (each gather instr spans one contiguous 6400B window),
// MLP=16, inline dtype probe, single fused kernel, deterministic last-block
// reduction (index-ordered, self-resetting ticket for graph replay).

#define NUM_TAGS 50
#define CHUNK    16                    // elements per lane -> 512 per warp
#define WELEM    (32 * CHUNK)          // 512
#define TPB      256
#define WPB      (TPB / 32)            // 8 warps/block
#define MAXBLK   4096
#define FULLM    0xFFFFFFFFu

__device__ double g_part[MAXBLK];
__device__ unsigned int g_done = 0;    // self-resetting ticket counter

__global__ void __launch_bounds__(TPB) k_fused(
    const float* __restrict__ logits,
    const void*  __restrict__ tags_raw,
    const float* __restrict__ transitions,
    float* __restrict__ out,
    int S)
{
    __shared__ float s_trans[NUM_TAGS * NUM_TAGS];
    __shared__ int   s_is64;
    __shared__ bool  s_last;

    // --- inline dtype probe: warp 0, 64 entries in parallel (L2-hot after blk 0) ---
    if (threadIdx.x < 32) {
        const long long* t64 = (const long long*)tags_raw;
        bool bad = false;
        #pragma unroll
        for (int k = 0; k < 2; k++) {
            int idx = threadIdx.x + 32 * k;
            if (idx < S) {
                long long v = t64[idx];
                bad |= (v < 0 || v >= NUM_TAGS);
            }
        }
        unsigned m = __ballot_sync(FULLM, bad);
        if (threadIdx.x == 0) s_is64 = (m == 0) ? 1 : 0;
    }

    // --- stage transitions in smem ---
    for (int i = threadIdx.x; i < NUM_TAGS * NUM_TAGS; i += TPB)
        s_trans[i] = transitions[i];
    __syncthreads();

    const int is64 = s_is64;
    const int lane = threadIdx.x & 31;
    const int warp = (blockIdx.x * WPB) + (threadIdx.x >> 5);
    const int base = warp * WELEM;

    float acc = 0.0f;

    if (base + WELEM < S) {
        // ---- fast path: full warp tile, boundary tags[base+512] exists ----
        int t[CHUNK];
        if (is64) {
            const long long* tg = (const long long*)tags_raw;
            #pragma unroll
            for (int j = 0; j < CHUNK; j++)
                t[j] = (int)tg[base + lane + 32 * j];      // coalesced per j
        } else {
            const int* tg = (const int*)tags_raw;
            #pragma unroll
            for (int j = 0; j < CHUNK; j++)
                t[j] = tg[base + lane + 32 * j];           // 1 line per instr
        }
        // boundary tag for lane31, j=CHUNK-1: element base+512
        int t_follow = 0;
        if (lane == 31)
            t_follow = is64 ? (int)((const long long*)tags_raw)[base + WELEM]
                            : ((const int*)tags_raw)[base + WELEM];

        // 16 independent gathers; each instr's 32 addrs span one 6400B window
        float e[CHUNK];
        #pragma unroll
        for (int j = 0; j < CHUNK; j++) {
            int i = base + lane + 32 * j;
            e[j] = __ldg(&logits[(long long)i * NUM_TAGS + t[j]]);
        }

        // transitions: partner tag of element i is element i+1 = (lane+1, j),
        // or (0, j+1) when lane==31, or t_follow at the very end.
        float tr = 0.0f;
        #pragma unroll
        for (int j = 0; j < CHUNK; j++) {
            int down = __shfl_down_sync(FULLM, t[j], 1);   // lane31 gets garbage
            int wrap;
            if (j < CHUNK - 1)
                wrap = __shfl_sync(FULLM, t[j + 1], 0);    // lane0's next-j tag
            else
                wrap = t_follow;                            // valid on lane31
            int tn = (lane == 31) ? wrap : down;
            tr += s_trans[t[j] * NUM_TAGS + tn];
        }

        #pragma unroll
        for (int j = 0; j < CHUNK; j++)
            acc += e[j];
        acc += tr;
    } else if (base < S) {
        // ---- tail: scalar per-lane loop ----
        if (is64) {
            const long long* tg = (const long long*)tags_raw;
            for (int i = base + lane; i < S; i += 32) {
                int tt = (int)tg[i];
                acc += logits[(long long)i * NUM_TAGS + tt];
                if (i + 1 < S)
                    acc += s_trans[tt * NUM_TAGS + (int)tg[i + 1]];
            }
        } else {
            const int* tg = (const int*)tags_raw;
            for (int i = base + lane; i < S; i += 32) {
                int tt = tg[i];
                acc += logits[(long long)i * NUM_TAGS + tt];
                if (i + 1 < S)
                    acc += s_trans[tt * NUM_TAGS + tg[i + 1]];
            }
        }
    }

    // --- block reduce ---
    #pragma unroll
    for (int off = 16; off > 0; off >>= 1)
        acc += __shfl_down_sync(FULLM, acc, off);

    __shared__ float s_warp[WPB];
    int wid = threadIdx.x >> 5;
    if (lane == 0) s_warp[wid] = acc;
    __syncthreads();
    if (wid == 0) {
        acc = (lane < WPB) ? s_warp[lane] : 0.0f;
        #pragma unroll
        for (int off = 4; off > 0; off >>= 1)
            acc += __shfl_down_sync(FULLM, acc, off);
        if (lane == 0)
            g_part[blockIdx.x] = (double)acc;
    }

    // --- last-block final reduction (index-ordered = deterministic) ---
    if (threadIdx.x == 0) {
        __threadfence();
        unsigned int ticket = atomicAdd(&g_done, 1u);
        s_last = (ticket == gridDim.x - 1);
    }
    __syncthreads();

    if (s_last) {
        __shared__ double s_red[WPB];
        double d = 0.0;
        for (int i = threadIdx.x; i < (int)gridDim.x; i += TPB)
            d += g_part[i];

        #pragma unroll
        for (int off = 16; off > 0; off >>= 1)
            d += __shfl_down_sync(FULLM, d, off);
        if (lane == 0) s_red[wid] = d;
        __syncthreads();
        if (wid == 0) {
            d = (lane < WPB) ? s_red[lane] : 0.0;
            #pragma unroll
            for (int off = 4; off > 0; off >>= 1)
                d += __shfl_down_sync(FULLM, d, off);
            if (lane == 0) {
                out[0] = (float)(-d);
                g_done = 0;            // reset for next graph replay
            }
        }
    }
}

extern "C" void kernel_launch(void* const* d_in, const int* in_sizes, int n_in,
                              void* d_out, int out_size) {
    const float* logits      = (const float*)d_in[0];
    const void*  tags        = d_in[1];
    const float* transitions = (const float*)d_in[2];
    float*       out         = (float*)d_out;

    const int S = in_sizes[1];  // tags element count = SEQ_LEN

    int warps  = (S + WELEM - 1) / WELEM;
    int blocks = (warps + WPB - 1) / WPB;
    if (blocks > MAXBLK) blocks = MAXBLK;
    k_fused<<<blocks, TPB>>>(logits, tags, transitions, out, S);
}

// round 17
// speedup vs baseline: 1.0061x; 1.0061x over previous
#include <cuda_runtime.h>
#include <cuda_bf16.h>

// CRF score: -( sum_i logits[i, tags[i]] + sum_{i>0} transitions[tags[i-1], tags[i]] )
// logits: [S, 50] f32, tags: [S] int (dtype auto-detected int32 vs int64, inline probe),
// transitions: [50, 50] f32. Output: scalar f32.
//
// FINAL, CONVERGED (47.6-47.9us across 9 runs, rel_err 0; best 47.616).
// DRAM random-request bound at the hardware floor:
//  - bytes: 2M mandatory 4B gathers -> ~1.9M distinct 128B-line fetches (~250MB),
//    invariant across 12 layout/cache-op measurements; granularity knob banned.
//  - rate: ~5.4TB/s at ~68% DRAM-busy, queues full from t~0 (all 3906 warps
//    chip-resident, ~62K requests materialized upfront) = bank-activate ceiling.
//  - no L2 reuse (lines hit ~1.05x); streaming >=56us; tag-width tricks save
//    nothing at line granularity; algorithmic reduction impossible.
// Warp-interleaved tiles (each gather instr spans one contiguous 6400B window),
// MLP=16, inline dtype probe, single fused kernel, deterministic last-block
// reduction (index-ordered, self-resetting ticket for graph replay).

#define NUM_TAGS 50
#define CHUNK    16                    // elements per lane -> 512 per warp
#define WELEM    (32 * CHUNK)          // 512
#define TPB      256
#define WPB      (TPB / 32)            // 8 warps/block
#define MAXBLK   4096
#define FULLM    0xFFFFFFFFu

__device__ double g_part[MAXBLK];
__device__ unsigned int g_done = 0;    // self-resetting ticket counter

__global__ void __launch_bounds__(TPB) k_fused(
    const float* __restrict__ logits,
    const void*  __restrict__ tags_raw,
    const float* __restrict__ transitions,
    float* __restrict__ out,
    int S)
{
    __shared__ float s_trans[NUM_TAGS * NUM_TAGS];
    __shared__ int   s_is64;
    __shared__ bool  s_last;

    // --- inline dtype probe: warp 0, 64 entries in parallel (L2-hot after blk 0) ---
    if (threadIdx.x < 32) {
        const long long* t64 = (const long long*)tags_raw;
        bool bad = false;
        #pragma unroll
        for (int k = 0; k < 2; k++) {
            int idx = threadIdx.x + 32 * k;
            if (idx < S) {
                long long v = t64[idx];
                bad |= (v < 0 || v >= NUM_TAGS);
            }
        }
        unsigned m = __ballot_sync(FULLM, bad);
        if (threadIdx.x == 0) s_is64 = (m == 0) ? 1 : 0;
    }

    // --- stage transitions in smem ---
    for (int i = threadIdx.x; i < NUM_TAGS * NUM_TAGS; i += TPB)
        s_trans[i] = transitions[i];
    __syncthreads();

    const int is64 = s_is64;
    const int lane = threadIdx.x & 31;
    const int warp = (blockIdx.x * WPB) + (threadIdx.x >> 5);
    const int base = warp * WELEM;

    float acc = 0.0f;

    if (base + WELEM < S) {
        // ---- fast path: full warp tile, boundary tags[base+512] exists ----
        int t[CHUNK];
        if (is64) {
            const long long* tg = (const long long*)tags_raw;
            #pragma unroll
            for (int j = 0; j < CHUNK; j++)
                t[j] = (int)tg[base + lane + 32 * j];      // coalesced per j
        } else {
            const int* tg = (const int*)tags_raw;
            #pragma unroll
            for (int j = 0; j < CHUNK; j++)
                t[j] = tg[base + lane + 32 * j];           // 1 line per instr
        }
        // boundary tag for lane31, j=CHUNK-1: element base+512
        int t_follow = 0;
        if (lane == 31)
            t_follow = is64 ? (int)((const long long*)tags_raw)[base + WELEM]
                            : ((const int*)tags_raw)[base + WELEM];

        // 16 independent gathers; each instr's 32 addrs span one 6400B window
        float e[CHUNK];
        #pragma unroll
        for (int j = 0; j < CHUNK; j++) {
            int i = base + lane + 32 * j;
            e[j] = __ldg(&logits[(long long)i * NUM_TAGS + t[j]]);
        }

        // transitions: partner tag of element i is element i+1 = (lane+1, j),
        // or (0, j+1) when lane==31, or t_follow at the very end.
        float tr = 0.0f;
        #pragma unroll
        for (int j = 0; j < CHUNK; j++) {
            int down = __shfl_down_sync(FULLM, t[j], 1);   // lane31 gets garbage
            int wrap;
            if (j < CHUNK - 1)
                wrap = __shfl_sync(FULLM, t[j + 1], 0);    // lane0's next-j tag
            else
                wrap = t_follow;                            // valid on lane31
            int tn = (lane == 31) ? wrap : down;
            tr += s_trans[t[j] * NUM_TAGS + tn];
        }

        #pragma unroll
        for (int j = 0; j < CHUNK; j++)
            acc += e[j];
        acc += tr;
    } else if (base < S) {
        // ---- tail: scalar per-lane loop ----
        if (is64) {
            const long long* tg = (const long long*)tags_raw;
            for (int i = base + lane; i < S; i += 32) {
                int tt = (int)tg[i];
                acc += logits[(long long)i * NUM_TAGS + tt];
                if (i + 1 < S)
                    acc += s_trans[tt * NUM_TAGS + (int)tg[i + 1]];
            }
        } else {
            const int* tg = (const int*)tags_raw;
            for (int i = base + lane; i < S; i += 32) {
                int tt = tg[i];
                acc += logits[(long long)i * NUM_TAGS + tt];
                if (i + 1 < S)
                    acc += s_trans[tt * NUM_TAGS + tg[i + 1]];
            }
        }
    }

    // --- block reduce ---
    #pragma unroll
    for (int off = 16; off > 0; off >>= 1)
        acc += __shfl_down_sync(FULLM, acc, off);

    __shared__ float s_warp[WPB];
    int wid = threadIdx.x >> 5;
    if (lane == 0) s_warp[wid] = acc;
    __syncthreads();
    if (wid == 0) {
        acc = (lane < WPB) ? s_warp[lane] : 0.0f;
        #pragma unroll
        for (int off = 4; off > 0; off >>= 1)
            acc += __shfl_down_sync(FULLM, acc, off);
        if (lane == 0)
            g_part[blockIdx.x] = (double)acc;
    }

    // --- last-block final reduction (index-ordered = deterministic) ---
    if (threadIdx.x == 0) {
        __threadfence();
        unsigned int ticket = atomicAdd(&g_done, 1u);
        s_last = (ticket == gridDim.x - 1);
    }
    __syncthreads();

    if (s_last) {
        __shared__ double s_red[WPB];
        double d = 0.0;
        for (int i = threadIdx.x; i < (int)gridDim.x; i += TPB)
            d += g_part[i];

        #pragma unroll
        for (int off = 16; off > 0; off >>= 1)
            d += __shfl_down_sync(FULLM, d, off);
        if (lane == 0) s_red[wid] = d;
        __syncthreads();
        if (wid == 0) {
            d = (lane < WPB) ? s_red[lane] : 0.0;
            #pragma unroll
            for (int off = 4; off > 0; off >>= 1)
                d += __shfl_down_sync(FULLM, d, off);
            if (lane == 0) {
                out[0] = (float)(-d);
                g_done = 0;            // reset for next graph replay
            }
        }
    }
}

extern "C" void kernel_launch(void* const* d_in, const int* in_sizes, int n_in,
                              void* d_out, int out_size) {
    const float* logits      = (const float*)d_in[0];
    const void*  tags        = d_in[1];
    const float* transitions = (const float*)d_in[2];
    float*       out         = (float*)d_out;

    const int S = in_sizes[1];  // tags element count = SEQ_LEN

    int warps  = (S + WELEM - 1) / WELEM;
    int blocks = (warps + WPB - 1) / WPB;
    if (blocks > MAXBLK) blocks = MAXBLK;
    k_fused<<<blocks, TPB>>>(logits, tags, transitions, out, S);
}